// round 9
// baseline (speedup 1.0000x reference)
#include <cuda_runtime.h>
#include <math.h>

#define NTOK 4096
#define DIM  1024
#define NEXP 8
#define CAP  1280
#define NSLOT (NTOK * 2)
#define ROWW (NEXP * CAP)            // 10240 floats per mask token-row

#define B_LOG   256                  // logits blocks (2 tokens/warp, 8 warps)
#define B_ZERO  2048                 // mask zero-fill blocks
#define B_BAT   (NEXP * CAP / 2)     // 5120 batch blocks (2 rows each)
#define ZERO0   (B_LOG + 1)          // 257
#define BAT0    (ZERO0 + B_ZERO)     // 2305
#define NBLK    (BAT0 + B_BAT)       // 7425

// Scratch (no device allocs allowed). All counters self-reset each launch.
__device__ int g_topidx[NSLOT];      // expert id per slot
__device__ int g_pos[NSLOT];         // position within expert, -1 if dropped
__device__ int g_inv[NEXP * CAP];    // (e,pos) -> token, -1 if empty
__device__ int g_done;               // logits blocks completed
__device__ int g_zero;               // zero blocks completed
__device__ int g_flag;               // scan complete
__device__ int g_bfin;               // batch blocks completed

__global__ __launch_bounds__(256, 4)
void k_moe(const float* __restrict__ x, const float* __restrict__ Wg,
           float* __restrict__ gates, float* __restrict__ mask,
           float* __restrict__ batch) {
    const int b = blockIdx.x;

    if (b >= BAT0) {
        // ----- exp_batches rows: wait for scan, then 2 rows/block -----
        if (threadIdx.x == 0) {
            while (atomicAdd(&g_flag, 0) == 0) __nanosleep(64);
        }
        __syncthreads();
        __threadfence();
        int r0 = (b - BAT0) * 2;
#pragma unroll
        for (int j = 0; j < 2; j++) {
            int r = r0 + j;
            int t = g_inv[r];
            float4 v = make_float4(0.f, 0.f, 0.f, 0.f);
            if (t >= 0)
                v = ((const float4*)x)[(size_t)t * (DIM / 4) + threadIdx.x];
            __stcs((float4*)batch + (size_t)r * (DIM / 4) + threadIdx.x, v);
        }
        __syncthreads();
        if (threadIdx.x == 0) {
            int n = atomicAdd(&g_bfin, 1);
            if (n == B_BAT - 1) {    // last batch block: reset for next replay
                g_flag = 0;
                g_bfin = 0;
            }
        }
        return;
    }

    if (b >= ZERO0) {
        // ----- mask zero-fill: independent, starts immediately -----
        int zb = b - ZERO0;                       // 0 .. 2047
        float4* dst = (float4*)mask + (size_t)zb * (256 * 20) + threadIdx.x;
        const float4 z = make_float4(0.f, 0.f, 0.f, 0.f);
#pragma unroll
        for (int j = 0; j < 20; j++)
            __stcs(dst + j * 256, z);
        __threadfence();
        __syncthreads();
        if (threadIdx.x == 0) atomicAdd(&g_zero, 1);
        return;
    }

    if (b < B_LOG) {
        // ----- logits: 2 tokens/warp, streamed x, W in shared -----
        __shared__ float4 sW[NEXP * DIM / 4];        // 32 KB
        const float4* W4 = (const float4*)Wg;
        for (int i = threadIdx.x; i < NEXP * DIM / 4; i += 256) sW[i] = W4[i];
        __syncthreads();

        int warp = threadIdx.x >> 5;
        int lane = threadIdx.x & 31;
        int t0 = (b * 8 + warp) * 2;

        const float4* xr = (const float4*)x + (size_t)t0 * (DIM / 4);
        float acc0[NEXP], acc1[NEXP];
#pragma unroll
        for (int e = 0; e < NEXP; e++) { acc0[e] = 0.f; acc1[e] = 0.f; }

#pragma unroll
        for (int i = 0; i < 8; i++) {
            int o = lane + 32 * i;
            float4 v0 = xr[o];
            float4 v1 = xr[256 + o];
#pragma unroll
            for (int e = 0; e < NEXP; e++) {
                float4 w = sW[e * 256 + o];
                acc0[e] += v0.x * w.x + v0.y * w.y + v0.z * w.z + v0.w * w.w;
                acc1[e] += v1.x * w.x + v1.y * w.y + v1.z * w.z + v1.w * w.w;
            }
        }
#pragma unroll
        for (int off = 16; off; off >>= 1)
#pragma unroll
            for (int e = 0; e < NEXP; e++) {
                acc0[e] += __shfl_xor_sync(0xffffffffu, acc0[e], off);
                acc1[e] += __shfl_xor_sync(0xffffffffu, acc1[e], off);
            }

        if (lane < 2) {
            int t = t0 + lane;
            float v1 = -1e30f, v2 = -1e30f;
            int i1 = 0, i2 = 0;
#pragma unroll
            for (int e = 0; e < NEXP; e++) {
                float a = lane ? acc1[e] : acc0[e];
                if (a > v1)      { v2 = v1; i2 = i1; v1 = a; i1 = e; }
                else if (a > v2) { v2 = a;  i2 = e; }
            }
            float e2 = expf(v2 - v1);
            float inv = 1.f / (1.f + e2);
            gates[2 * t]     = inv;
            gates[2 * t + 1] = e2 * inv;
            g_topidx[2 * t]     = i1;
            g_topidx[2 * t + 1] = i2;
        }
        __syncthreads();
        __threadfence();
        if (threadIdx.x == 0) atomicAdd(&g_done, 1);
        return;
    }

    // ----- scan block (b == B_LOG): wait logits -> positions -> flag;
    //       then wait zero-fill -> scatter gates into mask -----
    if (threadIdx.x == 0) {
        while (atomicAdd(&g_done, 0) < B_LOG) __nanosleep(64);
        g_done = 0;                                   // reset for next replay
    }
    __syncthreads();
    __threadfence();

    int tid = threadIdx.x;
    for (int i = tid; i < NEXP * CAP; i += 256) g_inv[i] = -1;

    int base = tid * 32;
    int e_loc[32];
    unsigned short h[NEXP];
#pragma unroll
    for (int e = 0; e < NEXP; e++) h[e] = 0;
#pragma unroll
    for (int j = 0; j < 32; j++) {
        int e = g_topidx[base + j];
        e_loc[j] = e;
        h[e]++;
    }

    __shared__ uint4 ssc[256];
    uint4 v;
    v.x = (unsigned)h[0] | ((unsigned)h[1] << 16);
    v.y = (unsigned)h[2] | ((unsigned)h[3] << 16);
    v.z = (unsigned)h[4] | ((unsigned)h[5] << 16);
    v.w = (unsigned)h[6] | ((unsigned)h[7] << 16);
    ssc[tid] = v;
    __syncthreads();
    for (int off = 1; off < 256; off <<= 1) {
        uint4 a = make_uint4(0, 0, 0, 0);
        if (tid >= off) a = ssc[tid - off];
        __syncthreads();
        v.x += a.x; v.y += a.y; v.z += a.z; v.w += a.w;
        ssc[tid] = v;
        __syncthreads();
    }

    int cnt[NEXP];
    cnt[0] = (int)(v.x & 0xFFFF) - (int)h[0];
    cnt[1] = (int)(v.x >> 16)    - (int)h[1];
    cnt[2] = (int)(v.y & 0xFFFF) - (int)h[2];
    cnt[3] = (int)(v.y >> 16)    - (int)h[3];
    cnt[4] = (int)(v.z & 0xFFFF) - (int)h[4];
    cnt[5] = (int)(v.z >> 16)    - (int)h[5];
    cnt[6] = (int)(v.w & 0xFFFF) - (int)h[6];
    cnt[7] = (int)(v.w >> 16)    - (int)h[7];

    int p_loc[32];
#pragma unroll
    for (int j = 0; j < 32; j++) {
        int slot = base + j;
        int e = e_loc[j];
        int p = cnt[e]++;
        if (p < CAP) {
            g_pos[slot] = p;
            g_inv[e * CAP + p] = slot >> 1;
            p_loc[j] = p;
        } else {
            g_pos[slot] = -1;
            p_loc[j] = -1;
        }
    }
    __threadfence();
    __syncthreads();
    if (threadIdx.x == 0) atomicExch(&g_flag, 1);     // release batch blocks

    // wait for all zero blocks, then scatter this thread's 32 gate values
    if (threadIdx.x == 0) {
        while (atomicAdd(&g_zero, 0) < B_ZERO) __nanosleep(128);
        g_zero = 0;                                   // reset for next replay
    }
    __syncthreads();
    __threadfence();
#pragma unroll
    for (int j = 0; j < 32; j++) {
        int p = p_loc[j];
        if (p >= 0) {
            int slot = base + j;
            int tok = slot >> 1;
            mask[(size_t)tok * ROWW + e_loc[j] * CAP + p] = gates[slot];
        }
    }
}

// ---------------------------------------------------------------------------
extern "C" void kernel_launch(void* const* d_in, const int* in_sizes, int n_in,
                              void* d_out, int out_size) {
    const float* x  = (const float*)d_in[0];   // [2,2048,1024] f32
    const float* Wg = (const float*)d_in[1];   // [8,1024] f32

    float* out   = (float*)d_out;
    float* gates = out;                                  // 8,192 floats
    float* mask  = out + (size_t)NSLOT;                  // 41,943,040 floats
    float* batch = mask + (size_t)NTOK * ROWW;           // 10,485,760 floats

    k_moe<<<NBLK, 256>>>(x, Wg, gates, mask, batch);
}